// round 1
// baseline (speedup 1.0000x reference)
#include <cuda_runtime.h>
#include <cuda_bf16.h>
#include <math.h>

#define BQ 2
#define S_LEN 2048
#define HK 16
#define HV 32
#define DK 128
#define DV 128
#define QKV 8192
#define NROWS (BQ * S_LEN)
#define TB 8   // tokens per smem batch in recurrence

// ---------------- scratch (device globals; no runtime allocation) ----------------
__device__ float g_qn[(size_t)NROWS * HK * DK];    // l2norm(q) * scale
__device__ float g_kn[(size_t)NROWS * HK * DK];    // l2norm(k)
__device__ float g_v [(size_t)NROWS * HV * DV];
__device__ float g_eg[(size_t)NROWS * HV];         // exp(g)
__device__ float g_bt[(size_t)NROWS * HV];         // sigmoid(b)

// ---------------- kernel 1: conv + silu + l2norm + gating ----------------
__global__ __launch_bounds__(256) void prep_kernel(
    const float* __restrict__ x,      // [NROWS, QKV]
    const float* __restrict__ bvec,   // [NROWS, HV]
    const float* __restrict__ avec,   // [NROWS, HV]
    const float* __restrict__ w,      // [QKV, 4]
    const float* __restrict__ dt_bias,// [HV]
    const float* __restrict__ alog)   // [HV]
{
    const int row = blockIdx.x;           // 0..NROWS-1
    const int s   = row & (S_LEN - 1);    // token within sequence
    const int tid = threadIdx.x;

    __shared__ float ysm[QKV];            // 32 KB

    // --- causal depthwise conv (width 4, zero history) + SiLU ---
    for (int base = tid * 4; base < QKV; base += 256 * 4) {
        float4 acc = make_float4(0.f, 0.f, 0.f, 0.f);
#pragma unroll
        for (int j = 0; j < 4; j++) {
            int sp = s - 3 + j;
            if (sp >= 0) {
                const float4 xv = *reinterpret_cast<const float4*>(
                    x + (size_t)(row - 3 + j) * QKV + base);
                acc.x = fmaf(xv.x, __ldg(w + (size_t)(base + 0) * 4 + j), acc.x);
                acc.y = fmaf(xv.y, __ldg(w + (size_t)(base + 1) * 4 + j), acc.y);
                acc.z = fmaf(xv.z, __ldg(w + (size_t)(base + 2) * 4 + j), acc.z);
                acc.w = fmaf(xv.w, __ldg(w + (size_t)(base + 3) * 4 + j), acc.w);
            }
        }
        // SiLU
        acc.x = acc.x / (1.f + __expf(-acc.x));
        acc.y = acc.y / (1.f + __expf(-acc.y));
        acc.z = acc.z / (1.f + __expf(-acc.z));
        acc.w = acc.w / (1.f + __expf(-acc.w));
        *reinterpret_cast<float4*>(ysm + base) = acc;
    }
    __syncthreads();

    const int wi   = tid >> 5;
    const int lane = tid & 31;
    const float qscale = 0.08838834764831845f; // 128^-0.5

    // --- l2 norms for 32 groups of 128 (16 q heads + 16 k heads) ---
    for (int gr = wi; gr < 32; gr += 8) {
        const float4 v4 = reinterpret_cast<const float4*>(ysm + gr * 128)[lane];
        float ss = v4.x * v4.x + v4.y * v4.y + v4.z * v4.z + v4.w * v4.w;
#pragma unroll
        for (int o = 16; o > 0; o >>= 1) ss += __shfl_xor_sync(0xffffffffu, ss, o);
        const bool isq = gr < 16;
        const float mul = rsqrtf(ss + 1e-6f) * (isq ? qscale : 1.f);
        float4 ov = make_float4(v4.x * mul, v4.y * mul, v4.z * mul, v4.w * mul);
        if (isq)
            reinterpret_cast<float4*>(g_qn + ((size_t)row * HK + gr) * DK)[lane] = ov;
        else
            reinterpret_cast<float4*>(g_kn + ((size_t)row * HK + (gr - 16)) * DK)[lane] = ov;
    }

    // --- v copy ---
    for (int i = tid * 4; i < HV * DV; i += 256 * 4)
        *reinterpret_cast<float4*>(g_v + (size_t)row * (HV * DV) + i) =
            *reinterpret_cast<const float4*>(ysm + 2 * HK * DK + i);

    // --- gating ---
    if (tid < HV) {
        const int h = tid;
        float aa = avec[(size_t)row * HV + h] + dt_bias[h];
        float sp = (aa > 20.f) ? aa : log1pf(expf(aa));    // softplus
        float g  = -expf(alog[h]) * sp;
        g_eg[(size_t)row * HV + h] = expf(g);
        float bb = bvec[(size_t)row * HV + h];
        g_bt[(size_t)row * HV + h] = 1.f / (1.f + expf(-bb));
    }
}

// ---------------- kernel 2: gated delta-rule recurrence ----------------
// grid: 128 blocks = (b, h, v-half). 256 threads = 64 chains x 4 k-slices.
// Each thread owns state s[k] for k in [p*32, p*32+32) of its chain (v column).
__global__ __launch_bounds__(256, 1) void rec_kernel(float* __restrict__ out)
{
    const int blk = blockIdx.x;
    const int b   = blk >> 6;          // 0..1
    const int h   = (blk >> 1) & 31;   // value head
    const int vh  = blk & 1;           // which 64 v-columns
    const int hk  = h >> 1;            // GQA: key head

    const int tid = threadIdx.x;
    const int c   = tid >> 2;          // chain 0..63 (lanes 4k..4k+3 share chain)
    const int p   = tid & 3;           // k-slice

    // padded stride 33 -> lanes with different p hit distinct banks
    __shared__ float sk[2][TB][4][33];
    __shared__ float sq[2][TB][4][33];
    __shared__ float sv[2][TB][64];
    __shared__ float sgb[2][TB][2];    // [0]=eg, [1]=beta

    float st[32];
#pragma unroll
    for (int i = 0; i < 32; i++) st[i] = 0.f;

    const float* qbase = g_qn + ((size_t)(b * S_LEN) * HK + hk) * DK;
    const float* kbase = g_kn + ((size_t)(b * S_LEN) * HK + hk) * DK;
    const float* vbase = g_v  + ((size_t)(b * S_LEN) * HV + h) * DV + vh * 64;
    const size_t qk_stride = (size_t)HK * DK;   // per-token stride in g_qn/g_kn
    const size_t v_stride  = (size_t)HV * DV;

    auto load_batch = [&](int buf, int t0) {
        for (int idx = tid; idx < TB * 128; idx += 256) {
            int tt = idx >> 7, d = idx & 127;
            sk[buf][tt][d >> 5][d & 31] = kbase[(size_t)(t0 + tt) * qk_stride + d];
            sq[buf][tt][d >> 5][d & 31] = qbase[(size_t)(t0 + tt) * qk_stride + d];
        }
        for (int idx = tid; idx < TB * 64; idx += 256) {
            int tt = idx >> 6, d = idx & 63;
            sv[buf][tt][d] = vbase[(size_t)(t0 + tt) * v_stride + d];
        }
        if (tid < TB * 2) {
            int tt = tid >> 1;
            size_t rg = (size_t)(b * S_LEN + t0 + tt) * HV + h;
            sgb[buf][tt][tid & 1] = (tid & 1) ? g_bt[rg] : g_eg[rg];
        }
    };

    load_batch(0, 0);
    __syncthreads();
    int buf = 0;

    float* outbase = out + ((size_t)(b * S_LEN) * HV + h) * DV + vh * 64 + c;

    for (int t0 = 0; t0 < S_LEN; t0 += TB) {
        if (t0 + TB < S_LEN) load_batch(buf ^ 1, t0 + TB);

#pragma unroll 1
        for (int tt = 0; tt < TB; tt++) {
            const float eg   = sgb[buf][tt][0];
            const float beta = sgb[buf][tt][1];
            const float* kp = &sk[buf][tt][p][0];
            const float* qp = &sq[buf][tt][p][0];

            float kr[32];
            float pp = 0.f;
#pragma unroll
            for (int i = 0; i < 32; i++) {
                kr[i] = kp[i];
                st[i] *= eg;
                pp = fmaf(kr[i], st[i], pp);
            }
            pp += __shfl_xor_sync(0xffffffffu, pp, 1);
            pp += __shfl_xor_sync(0xffffffffu, pp, 2);

            const float u = beta * (sv[buf][tt][c] - pp);

            float oo = 0.f;
#pragma unroll
            for (int i = 0; i < 32; i++) {
                st[i] = fmaf(kr[i], u, st[i]);
                oo = fmaf(qp[i], st[i], oo);
            }
            oo += __shfl_xor_sync(0xffffffffu, oo, 1);
            oo += __shfl_xor_sync(0xffffffffu, oo, 2);

            if (p == 0) outbase[(size_t)(t0 + tt) * (HV * DV)] = oo;
        }
        __syncthreads();
        buf ^= 1;
    }
}

// ---------------- launch ----------------
extern "C" void kernel_launch(void* const* d_in, const int* in_sizes, int n_in,
                              void* d_out, int out_size)
{
    const float* mixed_qkv = (const float*)d_in[0];
    const float* bvec      = (const float*)d_in[1];
    const float* avec      = (const float*)d_in[2];
    const float* convw     = (const float*)d_in[3];
    const float* dt_bias   = (const float*)d_in[4];
    const float* alog      = (const float*)d_in[5];
    // d_in[6] = cu_seqlens (equal-length; layout baked into constants)
    float* out = (float*)d_out;

    prep_kernel<<<NROWS, 256>>>(mixed_qkv, bvec, avec, convw, dt_bias, alog);
    rec_kernel<<<BQ * HV * 2, 256>>>(out);
}

// round 2
// speedup vs baseline: 1.4245x; 1.4245x over previous
#include <cuda_runtime.h>
#include <cuda_bf16.h>
#include <math.h>

#define BQ 2
#define S_LEN 2048
#define HK 16
#define HV 32
#define DK 128
#define DV 128
#define QKV 8192
#define NROWS (BQ * S_LEN)
#define TB 8   // tokens per smem batch in recurrence

// ---------------- scratch (device globals; no runtime allocation) ----------------
__device__ float g_qn[(size_t)NROWS * HK * DK];    // l2norm(q) * scale
__device__ float g_kn[(size_t)NROWS * HK * DK];    // l2norm(k)
__device__ float g_v [(size_t)NROWS * HV * DV];
__device__ float g_eg[(size_t)NROWS * HV];         // exp(g)
__device__ float g_bt[(size_t)NROWS * HV];         // sigmoid(b)

// ---------------- packed f32x2 helpers ----------------
__device__ __forceinline__ unsigned long long pack2(float lo, float hi) {
    unsigned long long r;
    asm("mov.b64 %0, {%1,%2};" : "=l"(r) : "f"(lo), "f"(hi));
    return r;
}
__device__ __forceinline__ float2 unpack2(unsigned long long v) {
    float2 r;
    asm("mov.b64 {%0,%1}, %2;" : "=f"(r.x), "=f"(r.y) : "l"(v));
    return r;
}
#define FMA2(d, a, b, c) asm("fma.rn.f32x2 %0, %1, %2, %3;" : "=l"(d) : "l"(a), "l"(b), "l"(c))
#define MUL2(d, a, b)    asm("mul.rn.f32x2 %0, %1, %2;"     : "=l"(d) : "l"(a), "l"(b))
#define ADD2(d, a, b)    asm("add.rn.f32x2 %0, %1, %2;"     : "=l"(d) : "l"(a), "l"(b))

union F4U { float4 f; unsigned long long u[2]; };

// ---------------- kernel 1: conv + silu + l2norm + gating ----------------
__global__ __launch_bounds__(256) void prep_kernel(
    const float* __restrict__ x,      // [NROWS, QKV]
    const float* __restrict__ bvec,   // [NROWS, HV]
    const float* __restrict__ avec,   // [NROWS, HV]
    const float* __restrict__ w,      // [QKV, 4]
    const float* __restrict__ dt_bias,// [HV]
    const float* __restrict__ alog)   // [HV]
{
    const int row = blockIdx.x;
    const int s   = row & (S_LEN - 1);
    const int tid = threadIdx.x;

    __shared__ float ysm[QKV];

    for (int base = tid * 4; base < QKV; base += 256 * 4) {
        float4 acc = make_float4(0.f, 0.f, 0.f, 0.f);
#pragma unroll
        for (int j = 0; j < 4; j++) {
            int sp = s - 3 + j;
            if (sp >= 0) {
                const float4 xv = *reinterpret_cast<const float4*>(
                    x + (size_t)(row - 3 + j) * QKV + base);
                acc.x = fmaf(xv.x, __ldg(w + (size_t)(base + 0) * 4 + j), acc.x);
                acc.y = fmaf(xv.y, __ldg(w + (size_t)(base + 1) * 4 + j), acc.y);
                acc.z = fmaf(xv.z, __ldg(w + (size_t)(base + 2) * 4 + j), acc.z);
                acc.w = fmaf(xv.w, __ldg(w + (size_t)(base + 3) * 4 + j), acc.w);
            }
        }
        acc.x = acc.x / (1.f + __expf(-acc.x));
        acc.y = acc.y / (1.f + __expf(-acc.y));
        acc.z = acc.z / (1.f + __expf(-acc.z));
        acc.w = acc.w / (1.f + __expf(-acc.w));
        *reinterpret_cast<float4*>(ysm + base) = acc;
    }
    __syncthreads();

    const int wi   = tid >> 5;
    const int lane = tid & 31;
    const float qscale = 0.08838834764831845f; // 128^-0.5

    for (int gr = wi; gr < 32; gr += 8) {
        const float4 v4 = reinterpret_cast<const float4*>(ysm + gr * 128)[lane];
        float ss = v4.x * v4.x + v4.y * v4.y + v4.z * v4.z + v4.w * v4.w;
#pragma unroll
        for (int o = 16; o > 0; o >>= 1) ss += __shfl_xor_sync(0xffffffffu, ss, o);
        const bool isq = gr < 16;
        const float mul = rsqrtf(ss + 1e-6f) * (isq ? qscale : 1.f);
        float4 ov = make_float4(v4.x * mul, v4.y * mul, v4.z * mul, v4.w * mul);
        if (isq)
            reinterpret_cast<float4*>(g_qn + ((size_t)row * HK + gr) * DK)[lane] = ov;
        else
            reinterpret_cast<float4*>(g_kn + ((size_t)row * HK + (gr - 16)) * DK)[lane] = ov;
    }

    for (int i = tid * 4; i < HV * DV; i += 256 * 4)
        *reinterpret_cast<float4*>(g_v + (size_t)row * (HV * DV) + i) =
            *reinterpret_cast<const float4*>(ysm + 2 * HK * DK + i);

    if (tid < HV) {
        const int h = tid;
        float aa = avec[(size_t)row * HV + h] + dt_bias[h];
        float sp = (aa > 20.f) ? aa : log1pf(expf(aa));
        float g  = -expf(alog[h]) * sp;
        g_eg[(size_t)row * HV + h] = expf(g);
        float bb = bvec[(size_t)row * HV + h];
        g_bt[(size_t)row * HV + h] = 1.f / (1.f + expf(-bb));
    }
}

// ---------------- kernel 2: gated delta-rule recurrence ----------------
// grid: 128 blocks = (b, h, v-half). 512 threads = 64 chains x 8 k-slices.
// Each thread owns 16 state values (8 packed f32x2 regs) of its chain.
// k/q smem layout: per token, 8 groups of 16 floats padded to stride 20
// -> LDS.128 by 8 p-lanes hits bank starts {0,20,8,28,16,4,24,12}: conflict-free.
__global__ __launch_bounds__(512, 1) void rec_kernel(float* __restrict__ out)
{
    const int blk = blockIdx.x;
    const int b   = blk >> 6;          // 0..1
    const int h   = (blk >> 1) & 31;   // value head
    const int vh  = blk & 1;           // which 64 v-columns
    const int hk  = h >> 1;            // GQA key head

    const int tid = threadIdx.x;
    const int c   = tid >> 3;          // chain 0..63
    const int p   = tid & 7;           // k-slice 0..7 (16 dims each)

    __shared__ float sk[2][TB][8][20];
    __shared__ float sq[2][TB][8][20];
    __shared__ float sv[2][TB][64];
    __shared__ float sgb[2][TB][2];    // [0]=eg, [1]=beta

    unsigned long long st2[8];
#pragma unroll
    for (int i = 0; i < 8; i++) st2[i] = 0ull;

    const float* qbase = g_qn + ((size_t)(b * S_LEN) * HK + hk) * DK;
    const float* kbase = g_kn + ((size_t)(b * S_LEN) * HK + hk) * DK;
    const float* vbase = g_v  + ((size_t)(b * S_LEN) * HV + h) * DV + vh * 64;
    const size_t qk_stride = (size_t)HK * DK;
    const size_t v_stride  = (size_t)HV * DV;

    auto load_batch = [&](int buf, int t0) {
        // k (threads 0..255) and q (threads 256..511): one float4 each
        if (tid < 256) {
            int tt = tid >> 5;
            int d  = (tid & 31) * 4;
            float4 val = *reinterpret_cast<const float4*>(
                kbase + (size_t)(t0 + tt) * qk_stride + d);
            *reinterpret_cast<float4*>(&sk[buf][tt][d >> 4][d & 15]) = val;
        } else {
            int t2 = tid - 256;
            int tt = t2 >> 5;
            int d  = (t2 & 31) * 4;
            float4 val = *reinterpret_cast<const float4*>(
                qbase + (size_t)(t0 + tt) * qk_stride + d);
            *reinterpret_cast<float4*>(&sq[buf][tt][d >> 4][d & 15]) = val;
        }
        // v: threads 0..127, one float4 each
        if (tid < 128) {
            int tt = tid >> 4;
            int d  = (tid & 15) * 4;
            *reinterpret_cast<float4*>(&sv[buf][tt][d]) =
                *reinterpret_cast<const float4*>(vbase + (size_t)(t0 + tt) * v_stride + d);
        }
        // gates: threads 0..15
        if (tid < TB * 2) {
            int tt = tid >> 1;
            size_t rg = (size_t)(b * S_LEN + t0 + tt) * HV + h;
            sgb[buf][tt][tid & 1] = (tid & 1) ? g_bt[rg] : g_eg[rg];
        }
    };

    load_batch(0, 0);
    __syncthreads();
    int buf = 0;

    float* outbase = out + ((size_t)(b * S_LEN) * HV + h) * DV + vh * 64 + c;

    for (int t0 = 0; t0 < S_LEN; t0 += TB) {
        if (t0 + TB < S_LEN) load_batch(buf ^ 1, t0 + TB);

#pragma unroll 1
        for (int tt = 0; tt < TB; tt++) {
            const float eg   = sgb[buf][tt][0];
            const float beta = sgb[buf][tt][1];
            const unsigned long long egp = pack2(eg, eg);

            const float* kp = &sk[buf][tt][p][0];
            const float* qp = &sq[buf][tt][p][0];
            F4U k0, k1, k2, k3, q0, q1, q2, q3;
            k0.f = *reinterpret_cast<const float4*>(kp + 0);
            k1.f = *reinterpret_cast<const float4*>(kp + 4);
            k2.f = *reinterpret_cast<const float4*>(kp + 8);
            k3.f = *reinterpret_cast<const float4*>(kp + 12);
            q0.f = *reinterpret_cast<const float4*>(qp + 0);
            q1.f = *reinterpret_cast<const float4*>(qp + 4);
            q2.f = *reinterpret_cast<const float4*>(qp + 8);
            q3.f = *reinterpret_cast<const float4*>(qp + 12);

            // --- decay state + pred = k . (eg*S) ---
            unsigned long long pa = 0ull, pb = 0ull;
            MUL2(st2[0], st2[0], egp);  FMA2(pa, k0.u[0], st2[0], pa);
            MUL2(st2[1], st2[1], egp);  FMA2(pb, k0.u[1], st2[1], pb);
            MUL2(st2[2], st2[2], egp);  FMA2(pa, k1.u[0], st2[2], pa);
            MUL2(st2[3], st2[3], egp);  FMA2(pb, k1.u[1], st2[3], pb);
            MUL2(st2[4], st2[4], egp);  FMA2(pa, k2.u[0], st2[4], pa);
            MUL2(st2[5], st2[5], egp);  FMA2(pb, k2.u[1], st2[5], pb);
            MUL2(st2[6], st2[6], egp);  FMA2(pa, k3.u[0], st2[6], pa);
            MUL2(st2[7], st2[7], egp);  FMA2(pb, k3.u[1], st2[7], pb);
            unsigned long long pc;
            ADD2(pc, pa, pb);
            float2 pf = unpack2(pc);
            float pp = pf.x + pf.y;
            pp += __shfl_xor_sync(0xffffffffu, pp, 1);
            pp += __shfl_xor_sync(0xffffffffu, pp, 2);
            pp += __shfl_xor_sync(0xffffffffu, pp, 4);

            const float u = beta * (sv[buf][tt][c] - pp);
            const unsigned long long up = pack2(u, u);

            // --- update S += k*u ; out = q . S ---
            unsigned long long oa = 0ull, ob = 0ull;
            FMA2(st2[0], k0.u[0], up, st2[0]);  FMA2(oa, q0.u[0], st2[0], oa);
            FMA2(st2[1], k0.u[1], up, st2[1]);  FMA2(ob, q0.u[1], st2[1], ob);
            FMA2(st2[2], k1.u[0], up, st2[2]);  FMA2(oa, q1.u[0], st2[2], oa);
            FMA2(st2[3], k1.u[1], up, st2[3]);  FMA2(ob, q1.u[1], st2[3], ob);
            FMA2(st2[4], k2.u[0], up, st2[4]);  FMA2(oa, q2.u[0], st2[4], oa);
            FMA2(st2[5], k2.u[1], up, st2[5]);  FMA2(ob, q2.u[1], st2[5], ob);
            FMA2(st2[6], k3.u[0], up, st2[6]);  FMA2(oa, q3.u[0], st2[6], oa);
            FMA2(st2[7], k3.u[1], up, st2[7]);  FMA2(ob, q3.u[1], st2[7], ob);
            unsigned long long oc;
            ADD2(oc, oa, ob);
            float2 of = unpack2(oc);
            float oo = of.x + of.y;
            oo += __shfl_xor_sync(0xffffffffu, oo, 1);
            oo += __shfl_xor_sync(0xffffffffu, oo, 2);
            oo += __shfl_xor_sync(0xffffffffu, oo, 4);

            if (p == 0) outbase[(size_t)(t0 + tt) * (HV * DV)] = oo;
        }
        __syncthreads();
        buf ^= 1;
    }
}

// ---------------- launch ----------------
extern "C" void kernel_launch(void* const* d_in, const int* in_sizes, int n_in,
                              void* d_out, int out_size)
{
    const float* mixed_qkv = (const float*)d_in[0];
    const float* bvec      = (const float*)d_in[1];
    const float* avec      = (const float*)d_in[2];
    const float* convw     = (const float*)d_in[3];
    const float* dt_bias   = (const float*)d_in[4];
    const float* alog      = (const float*)d_in[5];
    float* out = (float*)d_out;

    prep_kernel<<<NROWS, 256>>>(mixed_qkv, bvec, avec, convw, dt_bias, alog);
    rec_kernel<<<BQ * HV * 2, 512>>>(out);
}